// round 14
// baseline (speedup 1.0000x reference)
#include <cuda_runtime.h>
#include <cuda_bf16.h>
#include <cstdint>

#define NN 50000
#define NB ((NN + 255) / 256)   // 196

// ---------------- scratch ----------------
__device__ __align__(16) float g_deg[NN];
__device__ __align__(16) int   g_cnt[NN];
__device__ __align__(16) int   g_rowptr[NN + 1];
__device__ __align__(16) int   g_cursor[NN];
__device__ __align__(16) int   g_bsum[256];
__device__ __align__(16) int   g_csrsrc[600000];
__device__ __align__(16) float g_xw[(size_t)NN * 128];     // GEMM out / gather table
__device__ __align__(16) float g_zr[(size_t)NN * 128];     // z_pre
__device__ __align__(16) __nv_bfloat16 g_xh[(size_t)NN * 128],  g_xl[(size_t)NN * 128];   // x splits
__device__ __align__(16) __nv_bfloat16 g_hh[(size_t)NN * 128],  g_hl[(size_t)NN * 128];   // h splits
__device__ __align__(16) __nv_bfloat16 g_h1h[(size_t)NN * 128], g_h1l[(size_t)NN * 128];  // h1, later rh
__device__ __align__(16) __nv_bfloat16 g_cbh[(size_t)NN * 128], g_cbl[(size_t)NN * 128];  // emb splits
__device__ __align__(16) __nv_bfloat16 g_bthi[131072], g_btlo[131072];

__device__ __forceinline__ float sigmoidf_(float x) { return 1.0f / (1.0f + __expf(-x)); }

__device__ __forceinline__ uint32_t smem_u32(const void* p) {
    uint32_t a;
    asm("{ .reg .u64 t; cvta.to.shared.u64 t, %1; cvt.u32.u64 %0, t; }" : "=r"(a) : "l"(p));
    return a;
}
__device__ __forceinline__ void ldsm4(uint32_t& r0, uint32_t& r1, uint32_t& r2, uint32_t& r3,
                                      uint32_t addr) {
    asm volatile("ldmatrix.sync.aligned.m8n8.x4.shared.b16 {%0,%1,%2,%3}, [%4];"
                 : "=r"(r0), "=r"(r1), "=r"(r2), "=r"(r3) : "r"(addr));
}
__device__ __forceinline__ void mma16816(float* d, const uint32_t* a, uint32_t b0, uint32_t b1) {
    asm volatile(
        "mma.sync.aligned.m16n8k16.row.col.f32.bf16.bf16.f32 "
        "{%0,%1,%2,%3}, {%4,%5,%6,%7}, {%8,%9}, {%0,%1,%2,%3};"
        : "+f"(d[0]), "+f"(d[1]), "+f"(d[2]), "+f"(d[3])
        : "r"(a[0]), "r"(a[1]), "r"(a[2]), "r"(a[3]), "r"(b0), "r"(b1));
}
__device__ __forceinline__ uint32_t pk2(float x, float y, uint32_t& lo2) {
    __nv_bfloat16 hx = __float2bfloat16(x), hy = __float2bfloat16(y);
    __nv_bfloat16 lx = __float2bfloat16(x - __bfloat162float(hx));
    __nv_bfloat16 ly = __float2bfloat16(y - __bfloat162float(hy));
    lo2 = ((uint32_t)__bfloat16_as_ushort(ly) << 16) | __bfloat16_as_ushort(lx);
    return ((uint32_t)__bfloat16_as_ushort(hy) << 16) | __bfloat16_as_ushort(hx);
}

// ---------------- fused setup: zero cnt + weight split + x,h splits ----------------
// weight layout (bf16 elems):
//   0:      Win^T   128 rows, ldk 128
//   16384:  Whid^T  128 rows, ldk 128
//   32768:  [Wz|Wr]^T 256 rows, ldk 256
//   98304:  Wc^T    128 rows, ldk 256
__global__ void k_setup(const float* __restrict__ x, const float* __restrict__ h,
                        const float* __restrict__ Win, const float* __restrict__ Whid,
                        const float* __restrict__ Wz, const float* __restrict__ Wr,
                        const float* __restrict__ Wc) {
    int idx = blockIdx.x * blockDim.x + threadIdx.x;
    if (idx < NN) g_cnt[idx] = 0;
    if (idx < 131072) {
        float v; int dst;
        if (idx < 16384) {
            int k = idx >> 7, n = idx & 127;
            v = Win[idx]; dst = n * 128 + k;
        } else if (idx < 32768) {
            int i2 = idx - 16384; int k = i2 >> 7, n = i2 & 127;
            v = Whid[i2]; dst = 16384 + n * 128 + k;
        } else if (idx < 65536) {
            int i2 = idx - 32768; int k = i2 >> 7, n = i2 & 127;
            v = Wz[i2]; dst = 32768 + n * 256 + k;
        } else if (idx < 98304) {
            int i2 = idx - 65536; int k = i2 >> 7, n = i2 & 127;
            v = Wr[i2]; dst = 32768 + (128 + n) * 256 + k;
        } else {
            int i2 = idx - 98304; int k = i2 >> 7, n = i2 & 127;
            v = Wc[i2]; dst = 98304 + n * 256 + k;
        }
        __nv_bfloat16 hi = __float2bfloat16(v);
        __nv_bfloat16 lo = __float2bfloat16(v - __bfloat162float(hi));
        g_bthi[dst] = hi;
        g_btlo[dst] = lo;
    }
    if (idx < NN * 32) {
        float4 v = ((const float4*)x)[idx];
        uint32_t l0, l1;
        uint32_t h0 = pk2(v.x, v.y, l0);
        uint32_t h1 = pk2(v.z, v.w, l1);
        ((uint2*)g_xh)[idx] = make_uint2(h0, h1);
        ((uint2*)g_xl)[idx] = make_uint2(l0, l1);
        float4 w = ((const float4*)h)[idx];
        uint32_t m0, m1;
        uint32_t g0 = pk2(w.x, w.y, m0);
        uint32_t g1 = pk2(w.z, w.w, m1);
        ((uint2*)g_hh)[idx] = make_uint2(g0, g1);
        ((uint2*)g_hl)[idx] = make_uint2(m0, m1);
    }
}

// ---------------- CSR build ----------------
__global__ void k_hist(const int* __restrict__ dst, int E) {
    int i = blockIdx.x * blockDim.x + threadIdx.x;
    if (i < E) atomicAdd(&g_cnt[dst[i]], 1);
}
__global__ void k_scan_block() {
    __shared__ int sh[256];
    int tid = threadIdx.x;
    int i = blockIdx.x * 256 + tid;
    int v = (i < NN) ? g_cnt[i] : 0;
    sh[tid] = v;
    __syncthreads();
#pragma unroll
    for (int off = 1; off < 256; off <<= 1) {
        int t = (tid >= off) ? sh[tid - off] : 0;
        __syncthreads();
        sh[tid] += t;
        __syncthreads();
    }
    if (i < NN) g_rowptr[i] = sh[tid] - v;
    if (tid == 255) g_bsum[blockIdx.x] = sh[255];
}
__global__ void k_scan_fin(int E) {
    __shared__ int sh[256];
    int tid = threadIdx.x;
    int v = (tid < NB) ? g_bsum[tid] : 0;
    sh[tid] = v;
    __syncthreads();
#pragma unroll
    for (int off = 1; off < 256; off <<= 1) {
        int t = (tid >= off) ? sh[tid - off] : 0;
        __syncthreads();
        sh[tid] += t;
        __syncthreads();
    }
    __shared__ int s_off;
    if (tid == 0) s_off = sh[blockIdx.x] - g_bsum[blockIdx.x];
    __syncthreads();
    int i = blockIdx.x * 256 + tid;
    if (i >= NN) return;
    int r = g_rowptr[i] + s_off;
    g_rowptr[i] = r;
    g_cursor[i] = r;
    g_deg[i] = rsqrtf((float)(g_cnt[i] + 1));
    if (i == NN - 1) g_rowptr[NN] = E;
}
__global__ void k_scatter(const int* __restrict__ edge, int E) {
    int i = blockIdx.x * blockDim.x + threadIdx.x;
    if (i >= E) return;
    int d = edge[E + i];
    int pos = atomicAdd(&g_cursor[d], 1);
    g_csrsrc[pos] = edge[i];
}

// ---------------- HMMA GEMM: 64x64 tile, 128 thr, K-chunk 32, 80B pitch ----------------
#define PL 5120                    // 64 rows * 80 B
#define BUFS (4 * PL)              // 20480
#define GSMEM (2 * BUFS)           // 40960
#define AHI_O 0
#define ALO_O PL
#define BHI_O (2 * PL)
#define BLO_O (3 * PL)

// A given as two [M,128] plane pairs; chunks 0-3 read pair0, chunks 4-7 pair1 (KT=256).
// MODE 0: C = acc. MODE 3 (N=256): colg<128 -> zr; else rh = sigmoid(acc+br)*h -> splits.
// MODE 2: out = (1-u)*h + u*tanh(acc + bc), u = sigmoid(zr + bz)
template <int KT, int MODE>
__global__ __launch_bounds__(128, 5) void k_gemm64(
    const __nv_bfloat16* __restrict__ Ah0, const __nv_bfloat16* __restrict__ Al0,
    const __nv_bfloat16* __restrict__ Ah1, const __nv_bfloat16* __restrict__ Al1,
    const __nv_bfloat16* __restrict__ Bh, const __nv_bfloat16* __restrict__ Bl,
    int M, float* __restrict__ C,
    __nv_bfloat16* __restrict__ sph, __nv_bfloat16* __restrict__ spl,
    const float* __restrict__ p0, const float* __restrict__ p1,
    const float* __restrict__ p2, const float* __restrict__ p3)
{
    extern __shared__ char smem[];
    uint32_t sb = smem_u32(smem);
    int tid = threadIdx.x, lane = tid & 31, wid = tid >> 5;   // 4 warps, 2x2
    int wm = (wid >> 1) * 32, wn = (wid & 1) * 32;
    int bm = blockIdx.x * 64, bn = blockIdx.y * 64;

    float acc[2][4][4];
#pragma unroll
    for (int i = 0; i < 2; i++)
#pragma unroll
        for (int j = 0; j < 4; j++)
#pragma unroll
            for (int t = 0; t < 4; t++) acc[i][j][t] = 0.f;

    uint32_t aRow = lane & 15;
    uint32_t aK   = (lane >> 1) & 8;
    uint32_t bRow = (lane & 7) + ((lane >> 4) & 1) * 8;
    uint32_t bK   = ((lane >> 3) & 1) * 8;

    auto load_chunk = [&](int buf, int c) {
        uint32_t bufb = sb + buf * BUFS;
        const __nv_bfloat16* ah = (KT > 128 && c >= 4) ? Ah1 : Ah0;
        const __nv_bfloat16* al = (KT > 128 && c >= 4) ? Al1 : Al0;
        int ka = (c & 3) << 5;
        // A: 2 planes x 64 rows x 4 segs = 512 ops, 4/thread
#pragma unroll
        for (int it = 0; it < 4; it++) {
            int i = tid + it * 128;
            int plane = i >> 8;
            int rr = i & 255;
            int row = rr >> 2, seg = rr & 3;
            const __nv_bfloat16* g = plane ? al : ah;
            int gra = min(bm + row, M - 1);
            const __nv_bfloat16* src = g + (size_t)gra * 128 + ka + seg * 8;
            uint32_t dst = bufb + (plane ? ALO_O : AHI_O) + row * 80 + seg * 16;
            asm volatile("cp.async.cg.shared.global [%0], [%1], 16;" :: "r"(dst), "l"(src));
        }
        int kb = c << 5;
        // B: 2 planes x 64 rows x 4 segs = 512 ops, 4/thread
#pragma unroll
        for (int it = 0; it < 4; it++) {
            int i = tid + it * 128;
            int plane = i >> 8;
            int rr = i & 255;
            int row = rr >> 2, seg = rr & 3;
            const __nv_bfloat16* g = plane ? Bl : Bh;
            const __nv_bfloat16* src = g + (size_t)(bn + row) * KT + kb + seg * 8;
            uint32_t dst = bufb + (plane ? BLO_O : BHI_O) + row * 80 + seg * 16;
            asm volatile("cp.async.cg.shared.global [%0], [%1], 16;" :: "r"(dst), "l"(src));
        }
        asm volatile("cp.async.commit_group;" ::: "memory");
    };

    auto compute_chunk = [&](int buf) {
        uint32_t base = sb + buf * BUFS;
#pragma unroll
        for (int ks = 0; ks < 2; ks++) {
            uint32_t ah[2][4], al[2][4];
#pragma unroll
            for (int mt = 0; mt < 2; mt++) {
                uint32_t ao = base + AHI_O + (wm + mt * 16 + aRow) * 80 + (ks * 16 + aK) * 2;
                ldsm4(ah[mt][0], ah[mt][1], ah[mt][2], ah[mt][3], ao);
                ldsm4(al[mt][0], al[mt][1], al[mt][2], al[mt][3], ao + (ALO_O - AHI_O));
            }
#pragma unroll
            for (int np = 0; np < 2; np++) {
                uint32_t bo = base + BHI_O + (wn + np * 16 + bRow) * 80 + (ks * 16 + bK) * 2;
                uint32_t bh[4], bl[4];
                ldsm4(bh[0], bh[1], bh[2], bh[3], bo);
                ldsm4(bl[0], bl[1], bl[2], bl[3], bo + (BLO_O - BHI_O));
#pragma unroll
                for (int mt = 0; mt < 2; mt++) {
                    mma16816(acc[mt][np * 2],     ah[mt], bh[0], bh[1]);
                    mma16816(acc[mt][np * 2],     ah[mt], bl[0], bl[1]);
                    mma16816(acc[mt][np * 2],     al[mt], bh[0], bh[1]);
                    mma16816(acc[mt][np * 2 + 1], ah[mt], bh[2], bh[3]);
                    mma16816(acc[mt][np * 2 + 1], ah[mt], bl[2], bl[3]);
                    mma16816(acc[mt][np * 2 + 1], al[mt], bh[2], bh[3]);
                }
            }
        }
    };

    const int nc = KT >> 5;
    load_chunk(0, 0);
#pragma unroll
    for (int c = 0; c < nc; c++) {
        if (c + 1 < nc) {
            load_chunk((c + 1) & 1, c + 1);
            asm volatile("cp.async.wait_group 1;" ::: "memory");
        } else {
            asm volatile("cp.async.wait_group 0;" ::: "memory");
        }
        __syncthreads();
        compute_chunk(c & 1);
        __syncthreads();
    }

    // ---------------- epilogue ----------------
#pragma unroll
    for (int mt = 0; mt < 2; mt++)
#pragma unroll
        for (int nt = 0; nt < 4; nt++) {
            int colg = bn + wn + nt * 8 + ((lane & 3) << 1);
            int rbase = bm + wm + mt * 16 + (lane >> 2);
#pragma unroll
            for (int half = 0; half < 2; half++) {
                int row = rbase + half * 8;
                if (row >= M) continue;
                float vx = acc[mt][nt][half * 2];
                float vy = acc[mt][nt][half * 2 + 1];
                if (MODE == 0) {
                    *(float2*)&C[(size_t)row * 128 + colg] = make_float2(vx, vy);
                } else if (MODE == 3) {
                    if (colg < 128) {
                        *(float2*)&C[(size_t)row * 128 + colg] = make_float2(vx, vy);
                    } else {
                        int cc = colg - 128;
                        float2 hv = *(const float2*)&p0[(size_t)row * 128 + cc];
                        float2 bb = *(const float2*)&p1[cc];
                        float rx = sigmoidf_(vx + bb.x) * hv.x;
                        float ry = sigmoidf_(vy + bb.y) * hv.y;
                        uint32_t lo;
                        uint32_t hi = pk2(rx, ry, lo);
                        size_t idx = ((size_t)row * 128 + cc) >> 1;
                        ((uint32_t*)sph)[idx] = hi;
                        ((uint32_t*)spl)[idx] = lo;
                    }
                } else {  // MODE 2
                    size_t base = (size_t)row * 128 + colg;
                    float2 zp = *(const float2*)&p0[base];
                    float2 hv = *(const float2*)&p1[base];
                    float2 vbz = *(const float2*)&p2[colg];
                    float2 vbc = *(const float2*)&p3[colg];
                    float u0 = sigmoidf_(zp.x + vbz.x);
                    float u1 = sigmoidf_(zp.y + vbz.y);
                    float c0 = tanhf(vx + vbc.x);
                    float c1 = tanhf(vy + vbc.y);
                    *(float2*)&C[base] = make_float2((1.f - u0) * hv.x + u0 * c0,
                                                     (1.f - u1) * hv.y + u1 * c1);
                }
            }
        }
}

// ---------------- CSR aggregation: warp per dst node ----------------
template <int LAYER>
__global__ __launch_bounds__(256) void k_agg_csr(const float* __restrict__ b) {
    int w = blockIdx.x * 8 + (threadIdx.x >> 5);
    if (w >= NN) return;
    int lane = threadIdx.x & 31;
    const float4* xw4 = (const float4*)g_xw;

    float dd = g_deg[w];
    float4 acc = xw4[(size_t)w * 32 + lane];
    float cself = dd * dd;
    acc.x *= cself; acc.y *= cself; acc.z *= cself; acc.w *= cself;

    int start = g_rowptr[w], end = g_rowptr[w + 1];
    for (int base = start; base < end; base += 32) {
        int e = base + lane;
        int sv = 0; float dv = 0.f;
        if (e < end) { sv = g_csrsrc[e]; dv = g_deg[sv]; }
        int cnt = end - base; if (cnt > 32) cnt = 32;
        for (int j = 0; j < cnt; j++) {
            int s = __shfl_sync(0xffffffffu, sv, j);
            float c = __shfl_sync(0xffffffffu, dv, j) * dd;
            float4 v = xw4[(size_t)s * 32 + lane];
            acc.x += v.x * c; acc.y += v.y * c; acc.z += v.z * c; acc.w += v.w * c;
        }
    }

    float4 bb = *(const float4*)&b[lane * 4];
    acc.x += bb.x; acc.y += bb.y; acc.z += bb.z; acc.w += bb.w;
    if (LAYER == 1) {
        acc.x = fmaxf(acc.x, 0.f); acc.y = fmaxf(acc.y, 0.f);
        acc.z = fmaxf(acc.z, 0.f); acc.w = fmaxf(acc.w, 0.f);
    }
    uint32_t l0, l1;
    uint32_t h0 = pk2(acc.x, acc.y, l0);
    uint32_t h1 = pk2(acc.z, acc.w, l1);
    if (LAYER == 1) {
        ((uint2*)g_h1h)[(size_t)w * 32 + lane] = make_uint2(h0, h1);
        ((uint2*)g_h1l)[(size_t)w * 32 + lane] = make_uint2(l0, l1);
    } else {
        ((uint2*)g_cbh)[(size_t)w * 32 + lane] = make_uint2(h0, h1);
        ((uint2*)g_cbl)[(size_t)w * 32 + lane] = make_uint2(l0, l1);
    }
}

// ---------------- launcher ----------------
extern "C" void kernel_launch(void* const* d_in, const int* in_sizes, int n_in,
                              void* d_out, int out_size) {
    const float* x     = (const float*)d_in[0];
    const float* h     = (const float*)d_in[1];
    const int*   edge  = (const int*)d_in[2];
    const float* W_in  = (const float*)d_in[3];
    const float* b_in  = (const float*)d_in[4];
    const float* W_hid = (const float*)d_in[5];
    const float* b_hid = (const float*)d_in[6];
    const float* W_z   = (const float*)d_in[7];
    const float* b_z   = (const float*)d_in[8];
    const float* W_r   = (const float*)d_in[9];
    const float* b_r   = (const float*)d_in[10];
    const float* W_c   = (const float*)d_in[11];
    const float* b_c   = (const float*)d_in[12];
    float* out = (float*)d_out;

    const int N = in_sizes[0] / 128;
    const int E = in_sizes[2] / 2;

    float *p_xw, *p_zr;
    __nv_bfloat16 *p_bh, *p_bl, *p_xh, *p_xl, *p_hh, *p_hl, *p_h1h, *p_h1l, *p_cbh, *p_cbl;
    cudaGetSymbolAddress((void**)&p_xw,  g_xw);
    cudaGetSymbolAddress((void**)&p_zr,  g_zr);
    cudaGetSymbolAddress((void**)&p_bh,  g_bthi);
    cudaGetSymbolAddress((void**)&p_bl,  g_btlo);
    cudaGetSymbolAddress((void**)&p_xh,  g_xh);
    cudaGetSymbolAddress((void**)&p_xl,  g_xl);
    cudaGetSymbolAddress((void**)&p_hh,  g_hh);
    cudaGetSymbolAddress((void**)&p_hl,  g_hl);
    cudaGetSymbolAddress((void**)&p_h1h, g_h1h);
    cudaGetSymbolAddress((void**)&p_h1l, g_h1l);
    cudaGetSymbolAddress((void**)&p_cbh, g_cbh);
    cudaGetSymbolAddress((void**)&p_cbl, g_cbl);

    cudaFuncSetAttribute((const void*)k_gemm64<128, 0>, cudaFuncAttributeMaxDynamicSharedMemorySize, GSMEM);
    cudaFuncSetAttribute((const void*)k_gemm64<256, 3>, cudaFuncAttributeMaxDynamicSharedMemorySize, GSMEM);
    cudaFuncSetAttribute((const void*)k_gemm64<256, 2>, cudaFuncAttributeMaxDynamicSharedMemorySize, GSMEM);

    static cudaStream_t s1 = nullptr;
    static cudaEvent_t evA = nullptr, evCsr = nullptr;
    static bool tried = false;
    if (!tried) {
        tried = true;
        if (cudaStreamCreateWithFlags(&s1, cudaStreamNonBlocking) != cudaSuccess) s1 = nullptr;
        if (s1) {
            bool ok = cudaEventCreateWithFlags(&evA, cudaEventDisableTiming) == cudaSuccess &&
                      cudaEventCreateWithFlags(&evCsr, cudaEventDisableTiming) == cudaSuccess;
            if (!ok) s1 = nullptr;
        }
    }
    bool fork = (s1 != nullptr);
    cudaStream_t sSide = fork ? s1 : (cudaStream_t)0;

    const int T = 256;
    const int mt64 = (N + 63) / 64;       // 782
    dim3 g1(mt64, 2), g3(mt64, 4);        // 64-col n-tiles: 2 for N=128, 4 for N=256
    const int aggB = (NN + 7) / 8;

    // setup (stream 0): zero cnt + weight split + x,h splits
    k_setup<<<(NN * 32 + T - 1) / T, T>>>(x, h, W_in, W_hid, W_z, W_r, W_c);

    if (fork) { cudaEventRecord(evA, 0); cudaStreamWaitEvent(sSide, evA, 0); }

    // side lane: CSR build
    k_hist<<<(E + T - 1) / T, T, 0, sSide>>>(edge + E, E);
    k_scan_block<<<NB, 256, 0, sSide>>>();
    k_scan_fin<<<NB, 256, 0, sSide>>>(E);
    k_scatter<<<(E + T - 1) / T, T, 0, sSide>>>(edge, E);
    if (fork) cudaEventRecord(evCsr, sSide);

    // main lane
    k_gemm64<128, 0><<<g1, 128, GSMEM>>>(p_xh, p_xl, p_xh, p_xl, p_bh, p_bl, N,
                                         p_xw, nullptr, nullptr,
                                         nullptr, nullptr, nullptr, nullptr);
    if (fork) cudaStreamWaitEvent((cudaStream_t)0, evCsr, 0);
    k_agg_csr<1><<<aggB, T>>>(b_in);

    k_gemm64<128, 0><<<g1, 128, GSMEM>>>(p_h1h, p_h1l, p_h1h, p_h1l,
                                         p_bh + 16384, p_bl + 16384, N,
                                         p_xw, nullptr, nullptr,
                                         nullptr, nullptr, nullptr, nullptr);
    k_agg_csr<2><<<aggB, T>>>(b_hid);

    // gates: [z|r] = [emb|h] @ [Wz|Wr]; colg<128 -> zr; colg>=128 -> rh splits (reuse g_h1)
    k_gemm64<256, 3><<<g3, 128, GSMEM>>>(p_cbh, p_cbl, p_hh, p_hl,
                                         p_bh + 32768, p_bl + 32768, N,
                                         p_zr, p_h1h, p_h1l,
                                         h, b_r, nullptr, nullptr);

    // final: out = (1-u)*h + u*tanh([emb|rh]@Wc + b_c), u = sigmoid(zr + b_z)
    k_gemm64<256, 2><<<g1, 128, GSMEM>>>(p_cbh, p_cbl, p_h1h, p_h1l,
                                         p_bh + 98304, p_bl + 98304, N,
                                         out, nullptr, nullptr,
                                         p_zr, h, b_z, b_c);
}

// round 15
// speedup vs baseline: 1.1239x; 1.1239x over previous
#include <cuda_runtime.h>
#include <cuda_bf16.h>
#include <cstdint>

#define NN 50000
#define NB ((NN + 255) / 256)   // 196

// ---------------- scratch ----------------
__device__ __align__(16) float g_deg[NN];
__device__ __align__(16) int   g_cnt[NN];
__device__ __align__(16) int   g_rowptr[NN + 1];
__device__ __align__(16) int   g_cursor[NN];
__device__ __align__(16) int   g_bsum[256];
__device__ __align__(16) int   g_csrsrc[600000];
__device__ __align__(16) float g_xw[(size_t)NN * 128];     // GEMM out / gather table
__device__ __align__(16) float g_zr[(size_t)NN * 128];     // z_pre
__device__ __align__(16) __nv_bfloat16 g_xh[(size_t)NN * 128],  g_xl[(size_t)NN * 128];   // x splits
__device__ __align__(16) __nv_bfloat16 g_hh[(size_t)NN * 128],  g_hl[(size_t)NN * 128];   // h splits
__device__ __align__(16) __nv_bfloat16 g_h1h[(size_t)NN * 128], g_h1l[(size_t)NN * 128];  // h1, later rh
__device__ __align__(16) __nv_bfloat16 g_cbh[(size_t)NN * 128], g_cbl[(size_t)NN * 128];  // emb splits
__device__ __align__(16) __nv_bfloat16 g_bthi[131072], g_btlo[131072];

__device__ __forceinline__ float sigmoidf_(float x) { return 1.0f / (1.0f + __expf(-x)); }

__device__ __forceinline__ uint32_t smem_u32(const void* p) {
    uint32_t a;
    asm("{ .reg .u64 t; cvta.to.shared.u64 t, %1; cvt.u32.u64 %0, t; }" : "=r"(a) : "l"(p));
    return a;
}
__device__ __forceinline__ void ldsm4(uint32_t& r0, uint32_t& r1, uint32_t& r2, uint32_t& r3,
                                      uint32_t addr) {
    asm volatile("ldmatrix.sync.aligned.m8n8.x4.shared.b16 {%0,%1,%2,%3}, [%4];"
                 : "=r"(r0), "=r"(r1), "=r"(r2), "=r"(r3) : "r"(addr));
}
__device__ __forceinline__ void mma16816(float* d, const uint32_t* a, uint32_t b0, uint32_t b1) {
    asm volatile(
        "mma.sync.aligned.m16n8k16.row.col.f32.bf16.bf16.f32 "
        "{%0,%1,%2,%3}, {%4,%5,%6,%7}, {%8,%9}, {%0,%1,%2,%3};"
        : "+f"(d[0]), "+f"(d[1]), "+f"(d[2]), "+f"(d[3])
        : "r"(a[0]), "r"(a[1]), "r"(a[2]), "r"(a[3]), "r"(b0), "r"(b1));
}
__device__ __forceinline__ uint32_t pk2(float x, float y, uint32_t& lo2) {
    __nv_bfloat16 hx = __float2bfloat16(x), hy = __float2bfloat16(y);
    __nv_bfloat16 lx = __float2bfloat16(x - __bfloat162float(hx));
    __nv_bfloat16 ly = __float2bfloat16(y - __bfloat162float(hy));
    lo2 = ((uint32_t)__bfloat16_as_ushort(ly) << 16) | __bfloat16_as_ushort(lx);
    return ((uint32_t)__bfloat16_as_ushort(hy) << 16) | __bfloat16_as_ushort(hx);
}

// ---------------- setup (main): weight splits + x,h splits ----------------
// weight layout (bf16 elems):
//   0:      Win^T   128 rows, ldk 128
//   16384:  Whid^T  128 rows, ldk 128
//   32768:  [Wz|Wr]^T 256 rows, ldk 256
//   98304:  Wc^T    128 rows, ldk 256
__global__ void k_setup(const float* __restrict__ x, const float* __restrict__ h,
                        const float* __restrict__ Win, const float* __restrict__ Whid,
                        const float* __restrict__ Wz, const float* __restrict__ Wr,
                        const float* __restrict__ Wc) {
    int idx = blockIdx.x * blockDim.x + threadIdx.x;
    if (idx < 131072) {
        float v; int dst;
        if (idx < 16384) {
            int k = idx >> 7, n = idx & 127;
            v = Win[idx]; dst = n * 128 + k;
        } else if (idx < 32768) {
            int i2 = idx - 16384; int k = i2 >> 7, n = i2 & 127;
            v = Whid[i2]; dst = 16384 + n * 128 + k;
        } else if (idx < 65536) {
            int i2 = idx - 32768; int k = i2 >> 7, n = i2 & 127;
            v = Wz[i2]; dst = 32768 + n * 256 + k;
        } else if (idx < 98304) {
            int i2 = idx - 65536; int k = i2 >> 7, n = i2 & 127;
            v = Wr[i2]; dst = 32768 + (128 + n) * 256 + k;
        } else {
            int i2 = idx - 98304; int k = i2 >> 7, n = i2 & 127;
            v = Wc[i2]; dst = 98304 + n * 256 + k;
        }
        __nv_bfloat16 hi = __float2bfloat16(v);
        __nv_bfloat16 lo = __float2bfloat16(v - __bfloat162float(hi));
        g_bthi[dst] = hi;
        g_btlo[dst] = lo;
    }
    if (idx < NN * 32) {
        float4 v = ((const float4*)x)[idx];
        uint32_t l0, l1;
        uint32_t h0 = pk2(v.x, v.y, l0);
        uint32_t h1 = pk2(v.z, v.w, l1);
        ((uint2*)g_xh)[idx] = make_uint2(h0, h1);
        ((uint2*)g_xl)[idx] = make_uint2(l0, l1);
        float4 w = ((const float4*)h)[idx];
        uint32_t m0, m1;
        uint32_t g0 = pk2(w.x, w.y, m0);
        uint32_t g1 = pk2(w.z, w.w, m1);
        ((uint2*)g_hh)[idx] = make_uint2(g0, g1);
        ((uint2*)g_hl)[idx] = make_uint2(m0, m1);
    }
}

// ---------------- CSR build (side lane; independent of k_setup) ----------------
__global__ void k_zero_cnt() {
    int i = blockIdx.x * blockDim.x + threadIdx.x;
    if (i < NN) g_cnt[i] = 0;
}
__global__ void k_hist(const int* __restrict__ dst, int E) {
    int i = blockIdx.x * blockDim.x + threadIdx.x;
    if (i < E) atomicAdd(&g_cnt[dst[i]], 1);
}
__global__ void k_scan_block() {
    __shared__ int sh[256];
    int tid = threadIdx.x;
    int i = blockIdx.x * 256 + tid;
    int v = (i < NN) ? g_cnt[i] : 0;
    sh[tid] = v;
    __syncthreads();
#pragma unroll
    for (int off = 1; off < 256; off <<= 1) {
        int t = (tid >= off) ? sh[tid - off] : 0;
        __syncthreads();
        sh[tid] += t;
        __syncthreads();
    }
    if (i < NN) g_rowptr[i] = sh[tid] - v;
    if (tid == 255) g_bsum[blockIdx.x] = sh[255];
}
__global__ void k_scan_fin(int E) {
    __shared__ int sh[256];
    int tid = threadIdx.x;
    int v = (tid < NB) ? g_bsum[tid] : 0;
    sh[tid] = v;
    __syncthreads();
#pragma unroll
    for (int off = 1; off < 256; off <<= 1) {
        int t = (tid >= off) ? sh[tid - off] : 0;
        __syncthreads();
        sh[tid] += t;
        __syncthreads();
    }
    __shared__ int s_off;
    if (tid == 0) s_off = sh[blockIdx.x] - g_bsum[blockIdx.x];
    __syncthreads();
    int i = blockIdx.x * 256 + tid;
    if (i >= NN) return;
    int r = g_rowptr[i] + s_off;
    g_rowptr[i] = r;
    g_cursor[i] = r;
    g_deg[i] = rsqrtf((float)(g_cnt[i] + 1));
    if (i == NN - 1) g_rowptr[NN] = E;
}
__global__ void k_scatter(const int* __restrict__ edge, int E) {
    int i = blockIdx.x * blockDim.x + threadIdx.x;
    if (i >= E) return;
    int d = edge[E + i];
    int pos = atomicAdd(&g_cursor[d], 1);
    g_csrsrc[pos] = edge[i];
}

// ---------------- HMMA GEMM: 64x128 tile, chunk-indexed A plane pairs ----------------
#define PLA 5120
#define PLB 10240
#define BUFS (2 * PLA + 2 * PLB)
#define GSMEM (2 * BUFS)
#define AHI_O 0
#define ALO_O PLA
#define BHI_O (2 * PLA)
#define BLO_O (2 * PLA + PLB)

// A given as two [M,128] plane pairs; chunks 0-3 read pair0, chunks 4-7 pair1 (KT=256).
// MODE 0: C = acc. MODE 3: y0 -> zr; y1 -> rh = sigmoid(acc+br)*h -> splits.
// MODE 2: out = (1-u)*h + u*tanh(acc + bc), u = sigmoid(zr + bz)
template <int KT, int MODE>
__global__ __launch_bounds__(256, 3) void k_gemm64(
    const __nv_bfloat16* __restrict__ Ah0, const __nv_bfloat16* __restrict__ Al0,
    const __nv_bfloat16* __restrict__ Ah1, const __nv_bfloat16* __restrict__ Al1,
    const __nv_bfloat16* __restrict__ Bh, const __nv_bfloat16* __restrict__ Bl,
    int M, float* __restrict__ C,
    __nv_bfloat16* __restrict__ sph, __nv_bfloat16* __restrict__ spl,
    const float* __restrict__ p0, const float* __restrict__ p1,
    const float* __restrict__ p2, const float* __restrict__ p3)
{
    extern __shared__ char smem[];
    uint32_t sb = smem_u32(smem);
    int tid = threadIdx.x, lane = tid & 31, wid = tid >> 5;
    int wm = (wid >> 2) * 32, wn = (wid & 3) * 32;
    int bm = blockIdx.x * 64, bn = blockIdx.y * 128;

    float acc[2][4][4];
#pragma unroll
    for (int i = 0; i < 2; i++)
#pragma unroll
        for (int j = 0; j < 4; j++)
#pragma unroll
            for (int t = 0; t < 4; t++) acc[i][j][t] = 0.f;

    uint32_t aRow = lane & 15;
    uint32_t aK   = (lane >> 1) & 8;
    uint32_t bRow = (lane & 7) + ((lane >> 4) & 1) * 8;
    uint32_t bK   = ((lane >> 3) & 1) * 8;

    int arow = tid >> 2, aseg = tid & 3;

    auto load_chunk = [&](int buf, int c) {
        uint32_t bufb = sb + buf * BUFS;
        const __nv_bfloat16* ah = (KT > 128 && c >= 4) ? Ah1 : Ah0;
        const __nv_bfloat16* al = (KT > 128 && c >= 4) ? Al1 : Al0;
        int ka = (c & 3) << 5;
        int gra = min(bm + arow, M - 1);
        {
            const __nv_bfloat16* src = ah + (size_t)gra * 128 + ka + aseg * 8;
            uint32_t dst = bufb + AHI_O + arow * 80 + aseg * 16;
            asm volatile("cp.async.cg.shared.global [%0], [%1], 16;" :: "r"(dst), "l"(src));
        }
        {
            const __nv_bfloat16* src = al + (size_t)gra * 128 + ka + aseg * 8;
            uint32_t dst = bufb + ALO_O + arow * 80 + aseg * 16;
            asm volatile("cp.async.cg.shared.global [%0], [%1], 16;" :: "r"(dst), "l"(src));
        }
        int kb = c << 5;
#pragma unroll
        for (int it = 0; it < 2; it++) {
            int i = tid + it * 256;
            int row = i >> 2, seg = i & 3;
            const __nv_bfloat16* srch = Bh + (size_t)(bn + row) * KT + kb + seg * 8;
            const __nv_bfloat16* srcl = Bl + (size_t)(bn + row) * KT + kb + seg * 8;
            uint32_t dsth = bufb + BHI_O + row * 80 + seg * 16;
            uint32_t dstl = bufb + BLO_O + row * 80 + seg * 16;
            asm volatile("cp.async.cg.shared.global [%0], [%1], 16;" :: "r"(dsth), "l"(srch));
            asm volatile("cp.async.cg.shared.global [%0], [%1], 16;" :: "r"(dstl), "l"(srcl));
        }
        asm volatile("cp.async.commit_group;" ::: "memory");
    };

    auto compute_chunk = [&](int buf) {
        uint32_t base = sb + buf * BUFS;
#pragma unroll
        for (int ks = 0; ks < 2; ks++) {
            uint32_t ah[2][4], al[2][4];
#pragma unroll
            for (int mt = 0; mt < 2; mt++) {
                uint32_t ao = base + AHI_O + (wm + mt * 16 + aRow) * 80 + (ks * 16 + aK) * 2;
                ldsm4(ah[mt][0], ah[mt][1], ah[mt][2], ah[mt][3], ao);
                ldsm4(al[mt][0], al[mt][1], al[mt][2], al[mt][3], ao + (ALO_O - AHI_O));
            }
#pragma unroll
            for (int np = 0; np < 2; np++) {
                uint32_t bo = base + BHI_O + (wn + np * 16 + bRow) * 80 + (ks * 16 + bK) * 2;
                uint32_t bh[4], bl[4];
                ldsm4(bh[0], bh[1], bh[2], bh[3], bo);
                ldsm4(bl[0], bl[1], bl[2], bl[3], bo + (BLO_O - BHI_O));
#pragma unroll
                for (int mt = 0; mt < 2; mt++) {
                    mma16816(acc[mt][np * 2],     ah[mt], bh[0], bh[1]);
                    mma16816(acc[mt][np * 2],     ah[mt], bl[0], bl[1]);
                    mma16816(acc[mt][np * 2],     al[mt], bh[0], bh[1]);
                    mma16816(acc[mt][np * 2 + 1], ah[mt], bh[2], bh[3]);
                    mma16816(acc[mt][np * 2 + 1], ah[mt], bl[2], bl[3]);
                    mma16816(acc[mt][np * 2 + 1], al[mt], bh[2], bh[3]);
                }
            }
        }
    };

    const int nc = KT >> 5;
    load_chunk(0, 0);
#pragma unroll
    for (int c = 0; c < nc; c++) {
        if (c + 1 < nc) {
            load_chunk((c + 1) & 1, c + 1);
            asm volatile("cp.async.wait_group 1;" ::: "memory");
        } else {
            asm volatile("cp.async.wait_group 0;" ::: "memory");
        }
        __syncthreads();
        compute_chunk(c & 1);
        __syncthreads();
    }

    // ---------------- epilogue ----------------
#pragma unroll
    for (int mt = 0; mt < 2; mt++)
#pragma unroll
        for (int nt = 0; nt < 4; nt++) {
            int colg = bn + wn + nt * 8 + ((lane & 3) << 1);
            int rbase = bm + wm + mt * 16 + (lane >> 2);
#pragma unroll
            for (int half = 0; half < 2; half++) {
                int row = rbase + half * 8;
                if (row >= M) continue;
                float vx = acc[mt][nt][half * 2];
                float vy = acc[mt][nt][half * 2 + 1];
                if (MODE == 0) {
                    *(float2*)&C[(size_t)row * 128 + colg] = make_float2(vx, vy);
                } else if (MODE == 3) {
                    if (colg < 128) {
                        *(float2*)&C[(size_t)row * 128 + colg] = make_float2(vx, vy);
                    } else {
                        int cc = colg - 128;
                        float2 hv = *(const float2*)&p0[(size_t)row * 128 + cc];
                        float2 bb = *(const float2*)&p1[cc];
                        float rx = sigmoidf_(vx + bb.x) * hv.x;
                        float ry = sigmoidf_(vy + bb.y) * hv.y;
                        uint32_t lo;
                        uint32_t hi = pk2(rx, ry, lo);
                        size_t idx = ((size_t)row * 128 + cc) >> 1;
                        ((uint32_t*)sph)[idx] = hi;
                        ((uint32_t*)spl)[idx] = lo;
                    }
                } else {  // MODE 2
                    size_t base = (size_t)row * 128 + colg;
                    float2 zp = *(const float2*)&p0[base];
                    float2 hv = *(const float2*)&p1[base];
                    float2 vbz = *(const float2*)&p2[colg];
                    float2 vbc = *(const float2*)&p3[colg];
                    float u0 = sigmoidf_(zp.x + vbz.x);
                    float u1 = sigmoidf_(zp.y + vbz.y);
                    float c0 = tanhf(vx + vbc.x);
                    float c1 = tanhf(vy + vbc.y);
                    *(float2*)&C[base] = make_float2((1.f - u0) * hv.x + u0 * c0,
                                                     (1.f - u1) * hv.y + u1 * c1);
                }
            }
        }
}

// ---------------- CSR aggregation: warp per dst node ----------------
template <int LAYER>
__global__ __launch_bounds__(256) void k_agg_csr(const float* __restrict__ b) {
    int w = blockIdx.x * 8 + (threadIdx.x >> 5);
    if (w >= NN) return;
    int lane = threadIdx.x & 31;
    const float4* xw4 = (const float4*)g_xw;

    float dd = g_deg[w];
    float4 acc = xw4[(size_t)w * 32 + lane];
    float cself = dd * dd;
    acc.x *= cself; acc.y *= cself; acc.z *= cself; acc.w *= cself;

    int start = g_rowptr[w], end = g_rowptr[w + 1];
    for (int base = start; base < end; base += 32) {
        int e = base + lane;
        int sv = 0; float dv = 0.f;
        if (e < end) { sv = g_csrsrc[e]; dv = g_deg[sv]; }
        int cnt = end - base; if (cnt > 32) cnt = 32;
        for (int j = 0; j < cnt; j++) {
            int s = __shfl_sync(0xffffffffu, sv, j);
            float c = __shfl_sync(0xffffffffu, dv, j) * dd;
            float4 v = xw4[(size_t)s * 32 + lane];
            acc.x += v.x * c; acc.y += v.y * c; acc.z += v.z * c; acc.w += v.w * c;
        }
    }

    float4 bb = *(const float4*)&b[lane * 4];
    acc.x += bb.x; acc.y += bb.y; acc.z += bb.z; acc.w += bb.w;
    if (LAYER == 1) {
        acc.x = fmaxf(acc.x, 0.f); acc.y = fmaxf(acc.y, 0.f);
        acc.z = fmaxf(acc.z, 0.f); acc.w = fmaxf(acc.w, 0.f);
    }
    uint32_t l0, l1;
    uint32_t h0 = pk2(acc.x, acc.y, l0);
    uint32_t h1 = pk2(acc.z, acc.w, l1);
    if (LAYER == 1) {
        ((uint2*)g_h1h)[(size_t)w * 32 + lane] = make_uint2(h0, h1);
        ((uint2*)g_h1l)[(size_t)w * 32 + lane] = make_uint2(l0, l1);
    } else {
        ((uint2*)g_cbh)[(size_t)w * 32 + lane] = make_uint2(h0, h1);
        ((uint2*)g_cbl)[(size_t)w * 32 + lane] = make_uint2(l0, l1);
    }
}

// ---------------- launcher ----------------
extern "C" void kernel_launch(void* const* d_in, const int* in_sizes, int n_in,
                              void* d_out, int out_size) {
    const float* x     = (const float*)d_in[0];
    const float* h     = (const float*)d_in[1];
    const int*   edge  = (const int*)d_in[2];
    const float* W_in  = (const float*)d_in[3];
    const float* b_in  = (const float*)d_in[4];
    const float* W_hid = (const float*)d_in[5];
    const float* b_hid = (const float*)d_in[6];
    const float* W_z   = (const float*)d_in[7];
    const float* b_z   = (const float*)d_in[8];
    const float* W_r   = (const float*)d_in[9];
    const float* b_r   = (const float*)d_in[10];
    const float* W_c   = (const float*)d_in[11];
    const float* b_c   = (const float*)d_in[12];
    float* out = (float*)d_out;

    const int N = in_sizes[0] / 128;
    const int E = in_sizes[2] / 2;

    float *p_xw, *p_zr;
    __nv_bfloat16 *p_bh, *p_bl, *p_xh, *p_xl, *p_hh, *p_hl, *p_h1h, *p_h1l, *p_cbh, *p_cbl;
    cudaGetSymbolAddress((void**)&p_xw,  g_xw);
    cudaGetSymbolAddress((void**)&p_zr,  g_zr);
    cudaGetSymbolAddress((void**)&p_bh,  g_bthi);
    cudaGetSymbolAddress((void**)&p_bl,  g_btlo);
    cudaGetSymbolAddress((void**)&p_xh,  g_xh);
    cudaGetSymbolAddress((void**)&p_xl,  g_xl);
    cudaGetSymbolAddress((void**)&p_hh,  g_hh);
    cudaGetSymbolAddress((void**)&p_hl,  g_hl);
    cudaGetSymbolAddress((void**)&p_h1h, g_h1h);
    cudaGetSymbolAddress((void**)&p_h1l, g_h1l);
    cudaGetSymbolAddress((void**)&p_cbh, g_cbh);
    cudaGetSymbolAddress((void**)&p_cbl, g_cbl);

    cudaFuncSetAttribute((const void*)k_gemm64<128, 0>, cudaFuncAttributeMaxDynamicSharedMemorySize, GSMEM);
    cudaFuncSetAttribute((const void*)k_gemm64<256, 3>, cudaFuncAttributeMaxDynamicSharedMemorySize, GSMEM);
    cudaFuncSetAttribute((const void*)k_gemm64<256, 2>, cudaFuncAttributeMaxDynamicSharedMemorySize, GSMEM);

    static cudaStream_t s1 = nullptr;
    static cudaEvent_t evA = nullptr, evCsr = nullptr;
    static bool tried = false;
    if (!tried) {
        tried = true;
        if (cudaStreamCreateWithFlags(&s1, cudaStreamNonBlocking) != cudaSuccess) s1 = nullptr;
        if (s1) {
            bool ok = cudaEventCreateWithFlags(&evA, cudaEventDisableTiming) == cudaSuccess &&
                      cudaEventCreateWithFlags(&evCsr, cudaEventDisableTiming) == cudaSuccess;
            if (!ok) s1 = nullptr;
        }
    }
    bool fork = (s1 != nullptr);
    cudaStream_t sSide = fork ? s1 : (cudaStream_t)0;

    const int T = 256;
    const int mt64 = (N + 63) / 64;       // 782
    dim3 g1(mt64, 1), g2(mt64, 2);
    const int aggB = (NN + 7) / 8;

    // fork side stream FROM capture stream at t=0 (CSR chain is independent of k_setup)
    if (fork) { cudaEventRecord(evA, 0); cudaStreamWaitEvent(sSide, evA, 0); }

    // side lane: zero cnt + CSR build (starts immediately)
    k_zero_cnt<<<(NN + T - 1) / T, T, 0, sSide>>>();
    k_hist<<<(E + T - 1) / T, T, 0, sSide>>>(edge + E, E);
    k_scan_block<<<NB, 256, 0, sSide>>>();
    k_scan_fin<<<NB, 256, 0, sSide>>>(E);
    k_scatter<<<(E + T - 1) / T, T, 0, sSide>>>(edge, E);
    if (fork) cudaEventRecord(evCsr, sSide);

    // main lane: weight + x,h splits, then GEMM chain
    k_setup<<<(NN * 32 + T - 1) / T, T>>>(x, h, W_in, W_hid, W_z, W_r, W_c);

    k_gemm64<128, 0><<<g1, T, GSMEM>>>(p_xh, p_xl, p_xh, p_xl, p_bh, p_bl, N,
                                       p_xw, nullptr, nullptr,
                                       nullptr, nullptr, nullptr, nullptr);
    if (fork) cudaStreamWaitEvent((cudaStream_t)0, evCsr, 0);
    k_agg_csr<1><<<aggB, T>>>(b_in);

    k_gemm64<128, 0><<<g1, T, GSMEM>>>(p_h1h, p_h1l, p_h1h, p_h1l,
                                       p_bh + 16384, p_bl + 16384, N,
                                       p_xw, nullptr, nullptr,
                                       nullptr, nullptr, nullptr, nullptr);
    k_agg_csr<2><<<aggB, T>>>(b_hid);

    // gates: [z|r] = [emb|h] @ [Wz|Wr]; y0 -> zr; y1 -> rh splits (reuse g_h1 buffers)
    k_gemm64<256, 3><<<g2, T, GSMEM>>>(p_cbh, p_cbl, p_hh, p_hl,
                                       p_bh + 32768, p_bl + 32768, N,
                                       p_zr, p_h1h, p_h1l,
                                       h, b_r, nullptr, nullptr);

    // final: out = (1-u)*h + u*tanh([emb|rh]@Wc + b_c), u = sigmoid(zr + b_z)
    k_gemm64<256, 2><<<g1, T, GSMEM>>>(p_cbh, p_cbl, p_h1h, p_h1l,
                                       p_bh + 98304, p_bl + 98304, N,
                                       out, nullptr, nullptr,
                                       p_zr, h, b_z, b_c);
}

// round 16
// speedup vs baseline: 1.1496x; 1.0228x over previous
#include <cuda_runtime.h>
#include <cuda_bf16.h>
#include <cstdint>

#define NN 50000
#define NB ((NN + 255) / 256)   // 196

// ---------------- scratch ----------------
__device__ __align__(16) float g_deg[NN];
__device__ __align__(16) int   g_cnt[NN];
__device__ __align__(16) int   g_rowptr[NN + 1];
__device__ __align__(16) int   g_cursor[NN];
__device__ __align__(16) int   g_bsum[256];
__device__ __align__(16) int   g_csrsrc[600000];
__device__ __align__(16) float g_xw[(size_t)NN * 128];     // GEMM out / gather table
__device__ __align__(16) float g_zr[(size_t)NN * 128];     // u = sigmoid(z_pre + b_z)
__device__ __align__(16) __nv_bfloat16 g_xh[(size_t)NN * 128],  g_xl[(size_t)NN * 128];   // x splits
__device__ __align__(16) __nv_bfloat16 g_hh[(size_t)NN * 128],  g_hl[(size_t)NN * 128];   // h splits
__device__ __align__(16) __nv_bfloat16 g_h1h[(size_t)NN * 128], g_h1l[(size_t)NN * 128];  // h1, later rh
__device__ __align__(16) __nv_bfloat16 g_cbh[(size_t)NN * 128], g_cbl[(size_t)NN * 128];  // emb splits
__device__ __align__(16) __nv_bfloat16 g_bthi[131072], g_btlo[131072];

__device__ __forceinline__ float sigmoidf_(float x) { return 1.0f / (1.0f + __expf(-x)); }

__device__ __forceinline__ uint32_t smem_u32(const void* p) {
    uint32_t a;
    asm("{ .reg .u64 t; cvta.to.shared.u64 t, %1; cvt.u32.u64 %0, t; }" : "=r"(a) : "l"(p));
    return a;
}
__device__ __forceinline__ void ldsm4(uint32_t& r0, uint32_t& r1, uint32_t& r2, uint32_t& r3,
                                      uint32_t addr) {
    asm volatile("ldmatrix.sync.aligned.m8n8.x4.shared.b16 {%0,%1,%2,%3}, [%4];"
                 : "=r"(r0), "=r"(r1), "=r"(r2), "=r"(r3) : "r"(addr));
}
__device__ __forceinline__ void mma16816(float* d, const uint32_t* a, uint32_t b0, uint32_t b1) {
    asm volatile(
        "mma.sync.aligned.m16n8k16.row.col.f32.bf16.bf16.f32 "
        "{%0,%1,%2,%3}, {%4,%5,%6,%7}, {%8,%9}, {%0,%1,%2,%3};"
        : "+f"(d[0]), "+f"(d[1]), "+f"(d[2]), "+f"(d[3])
        : "r"(a[0]), "r"(a[1]), "r"(a[2]), "r"(a[3]), "r"(b0), "r"(b1));
}
__device__ __forceinline__ uint32_t pk2(float x, float y, uint32_t& lo2) {
    __nv_bfloat16 hx = __float2bfloat16(x), hy = __float2bfloat16(y);
    __nv_bfloat16 lx = __float2bfloat16(x - __bfloat162float(hx));
    __nv_bfloat16 ly = __float2bfloat16(y - __bfloat162float(hy));
    lo2 = ((uint32_t)__bfloat16_as_ushort(ly) << 16) | __bfloat16_as_ushort(lx);
    return ((uint32_t)__bfloat16_as_ushort(hy) << 16) | __bfloat16_as_ushort(hx);
}

// ---------------- fused setup: zero cnt + weight split + x,h splits ----------------
// weight layout (bf16 elems):
//   0:      Win^T   128 rows, ldk 128
//   16384:  Whid^T  128 rows, ldk 128
//   32768:  [Wz|Wr]^T 256 rows, ldk 256
//   98304:  Wc^T    128 rows, ldk 256
__global__ void k_setup(const float* __restrict__ x, const float* __restrict__ h,
                        const float* __restrict__ Win, const float* __restrict__ Whid,
                        const float* __restrict__ Wz, const float* __restrict__ Wr,
                        const float* __restrict__ Wc) {
    int idx = blockIdx.x * blockDim.x + threadIdx.x;
    if (idx < NN) g_cnt[idx] = 0;
    if (idx < 131072) {
        float v; int dst;
        if (idx < 16384) {
            int k = idx >> 7, n = idx & 127;
            v = Win[idx]; dst = n * 128 + k;
        } else if (idx < 32768) {
            int i2 = idx - 16384; int k = i2 >> 7, n = i2 & 127;
            v = Whid[i2]; dst = 16384 + n * 128 + k;
        } else if (idx < 65536) {
            int i2 = idx - 32768; int k = i2 >> 7, n = i2 & 127;
            v = Wz[i2]; dst = 32768 + n * 256 + k;
        } else if (idx < 98304) {
            int i2 = idx - 65536; int k = i2 >> 7, n = i2 & 127;
            v = Wr[i2]; dst = 32768 + (128 + n) * 256 + k;
        } else {
            int i2 = idx - 98304; int k = i2 >> 7, n = i2 & 127;
            v = Wc[i2]; dst = 98304 + n * 256 + k;
        }
        __nv_bfloat16 hi = __float2bfloat16(v);
        __nv_bfloat16 lo = __float2bfloat16(v - __bfloat162float(hi));
        g_bthi[dst] = hi;
        g_btlo[dst] = lo;
    }
    if (idx < NN * 32) {
        float4 v = ((const float4*)x)[idx];
        uint32_t l0, l1;
        uint32_t h0 = pk2(v.x, v.y, l0);
        uint32_t h1 = pk2(v.z, v.w, l1);
        ((uint2*)g_xh)[idx] = make_uint2(h0, h1);
        ((uint2*)g_xl)[idx] = make_uint2(l0, l1);
        float4 w = ((const float4*)h)[idx];
        uint32_t m0, m1;
        uint32_t g0 = pk2(w.x, w.y, m0);
        uint32_t g1 = pk2(w.z, w.w, m1);
        ((uint2*)g_hh)[idx] = make_uint2(g0, g1);
        ((uint2*)g_hl)[idx] = make_uint2(m0, m1);
    }
}

// ---------------- CSR build ----------------
__global__ void k_hist(const int* __restrict__ dst, int E) {
    int i = blockIdx.x * blockDim.x + threadIdx.x;
    if (i < E) atomicAdd(&g_cnt[dst[i]], 1);
}
__global__ void k_scan_block() {
    __shared__ int sh[256];
    int tid = threadIdx.x;
    int i = blockIdx.x * 256 + tid;
    int v = (i < NN) ? g_cnt[i] : 0;
    sh[tid] = v;
    __syncthreads();
#pragma unroll
    for (int off = 1; off < 256; off <<= 1) {
        int t = (tid >= off) ? sh[tid - off] : 0;
        __syncthreads();
        sh[tid] += t;
        __syncthreads();
    }
    if (i < NN) g_rowptr[i] = sh[tid] - v;
    if (tid == 255) g_bsum[blockIdx.x] = sh[255];
}
__global__ void k_scan_fin(int E) {
    __shared__ int sh[256];
    int tid = threadIdx.x;
    int v = (tid < NB) ? g_bsum[tid] : 0;
    sh[tid] = v;
    __syncthreads();
#pragma unroll
    for (int off = 1; off < 256; off <<= 1) {
        int t = (tid >= off) ? sh[tid - off] : 0;
        __syncthreads();
        sh[tid] += t;
        __syncthreads();
    }
    __shared__ int s_off;
    if (tid == 0) s_off = sh[blockIdx.x] - g_bsum[blockIdx.x];
    __syncthreads();
    int i = blockIdx.x * 256 + tid;
    if (i >= NN) return;
    int r = g_rowptr[i] + s_off;
    g_rowptr[i] = r;
    g_cursor[i] = r;
    g_deg[i] = rsqrtf((float)(g_cnt[i] + 1));
    if (i == NN - 1) g_rowptr[NN] = E;
}
__global__ void k_scatter(const int* __restrict__ edge, int E) {
    int i = blockIdx.x * blockDim.x + threadIdx.x;
    if (i >= E) return;
    int d = edge[E + i];
    int pos = atomicAdd(&g_cursor[d], 1);
    g_csrsrc[pos] = edge[i];
}

// ---------------- HMMA GEMM: 64x128 tile, chunk-indexed A plane pairs ----------------
#define PLA 5120
#define PLB 10240
#define BUFS (2 * PLA + 2 * PLB)
#define GSMEM (2 * BUFS)
#define AHI_O 0
#define ALO_O PLA
#define BHI_O (2 * PLA)
#define BLO_O (2 * PLA + PLB)

// A given as two [M,128] plane pairs; chunks 0-3 read pair0, chunks 4-7 pair1 (KT=256).
// MODE 0: C = acc.
// MODE 3: y0 -> u = sigmoid(acc + bz); y1 -> rh = sigmoid(acc + br)*h -> splits.
// MODE 2: out = (1-u)*h + u*tanh(acc + bc)   (u precomputed in zr)
template <int KT, int MODE>
__global__ __launch_bounds__(256, 3) void k_gemm64(
    const __nv_bfloat16* __restrict__ Ah0, const __nv_bfloat16* __restrict__ Al0,
    const __nv_bfloat16* __restrict__ Ah1, const __nv_bfloat16* __restrict__ Al1,
    const __nv_bfloat16* __restrict__ Bh, const __nv_bfloat16* __restrict__ Bl,
    int M, float* __restrict__ C,
    __nv_bfloat16* __restrict__ sph, __nv_bfloat16* __restrict__ spl,
    const float* __restrict__ p0, const float* __restrict__ p1,
    const float* __restrict__ p2, const float* __restrict__ p3)
{
    extern __shared__ char smem[];
    uint32_t sb = smem_u32(smem);
    int tid = threadIdx.x, lane = tid & 31, wid = tid >> 5;
    int wm = (wid >> 2) * 32, wn = (wid & 3) * 32;
    int bm = blockIdx.x * 64, bn = blockIdx.y * 128;

    float acc[2][4][4];
#pragma unroll
    for (int i = 0; i < 2; i++)
#pragma unroll
        for (int j = 0; j < 4; j++)
#pragma unroll
            for (int t = 0; t < 4; t++) acc[i][j][t] = 0.f;

    uint32_t aRow = lane & 15;
    uint32_t aK   = (lane >> 1) & 8;
    uint32_t bRow = (lane & 7) + ((lane >> 4) & 1) * 8;
    uint32_t bK   = ((lane >> 3) & 1) * 8;

    int arow = tid >> 2, aseg = tid & 3;

    auto load_chunk = [&](int buf, int c) {
        uint32_t bufb = sb + buf * BUFS;
        const __nv_bfloat16* ah = (KT > 128 && c >= 4) ? Ah1 : Ah0;
        const __nv_bfloat16* al = (KT > 128 && c >= 4) ? Al1 : Al0;
        int ka = (c & 3) << 5;
        int gra = min(bm + arow, M - 1);
        {
            const __nv_bfloat16* src = ah + (size_t)gra * 128 + ka + aseg * 8;
            uint32_t dst = bufb + AHI_O + arow * 80 + aseg * 16;
            asm volatile("cp.async.cg.shared.global [%0], [%1], 16;" :: "r"(dst), "l"(src));
        }
        {
            const __nv_bfloat16* src = al + (size_t)gra * 128 + ka + aseg * 8;
            uint32_t dst = bufb + ALO_O + arow * 80 + aseg * 16;
            asm volatile("cp.async.cg.shared.global [%0], [%1], 16;" :: "r"(dst), "l"(src));
        }
        int kb = c << 5;
#pragma unroll
        for (int it = 0; it < 2; it++) {
            int i = tid + it * 256;
            int row = i >> 2, seg = i & 3;
            const __nv_bfloat16* srch = Bh + (size_t)(bn + row) * KT + kb + seg * 8;
            const __nv_bfloat16* srcl = Bl + (size_t)(bn + row) * KT + kb + seg * 8;
            uint32_t dsth = bufb + BHI_O + row * 80 + seg * 16;
            uint32_t dstl = bufb + BLO_O + row * 80 + seg * 16;
            asm volatile("cp.async.cg.shared.global [%0], [%1], 16;" :: "r"(dsth), "l"(srch));
            asm volatile("cp.async.cg.shared.global [%0], [%1], 16;" :: "r"(dstl), "l"(srcl));
        }
        asm volatile("cp.async.commit_group;" ::: "memory");
    };

    auto compute_chunk = [&](int buf) {
        uint32_t base = sb + buf * BUFS;
#pragma unroll
        for (int ks = 0; ks < 2; ks++) {
            uint32_t ah[2][4], al[2][4];
#pragma unroll
            for (int mt = 0; mt < 2; mt++) {
                uint32_t ao = base + AHI_O + (wm + mt * 16 + aRow) * 80 + (ks * 16 + aK) * 2;
                ldsm4(ah[mt][0], ah[mt][1], ah[mt][2], ah[mt][3], ao);
                ldsm4(al[mt][0], al[mt][1], al[mt][2], al[mt][3], ao + (ALO_O - AHI_O));
            }
#pragma unroll
            for (int np = 0; np < 2; np++) {
                uint32_t bo = base + BHI_O + (wn + np * 16 + bRow) * 80 + (ks * 16 + bK) * 2;
                uint32_t bh[4], bl[4];
                ldsm4(bh[0], bh[1], bh[2], bh[3], bo);
                ldsm4(bl[0], bl[1], bl[2], bl[3], bo + (BLO_O - BHI_O));
#pragma unroll
                for (int mt = 0; mt < 2; mt++) {
                    mma16816(acc[mt][np * 2],     ah[mt], bh[0], bh[1]);
                    mma16816(acc[mt][np * 2],     ah[mt], bl[0], bl[1]);
                    mma16816(acc[mt][np * 2],     al[mt], bh[0], bh[1]);
                    mma16816(acc[mt][np * 2 + 1], ah[mt], bh[2], bh[3]);
                    mma16816(acc[mt][np * 2 + 1], ah[mt], bl[2], bl[3]);
                    mma16816(acc[mt][np * 2 + 1], al[mt], bh[2], bh[3]);
                }
            }
        }
    };

    const int nc = KT >> 5;
    load_chunk(0, 0);
#pragma unroll
    for (int c = 0; c < nc; c++) {
        if (c + 1 < nc) {
            load_chunk((c + 1) & 1, c + 1);
            asm volatile("cp.async.wait_group 1;" ::: "memory");
        } else {
            asm volatile("cp.async.wait_group 0;" ::: "memory");
        }
        __syncthreads();
        compute_chunk(c & 1);
        __syncthreads();
    }

    // ---------------- epilogue ----------------
#pragma unroll
    for (int mt = 0; mt < 2; mt++)
#pragma unroll
        for (int nt = 0; nt < 4; nt++) {
            int colg = bn + wn + nt * 8 + ((lane & 3) << 1);
            int rbase = bm + wm + mt * 16 + (lane >> 2);
#pragma unroll
            for (int half = 0; half < 2; half++) {
                int row = rbase + half * 8;
                if (row >= M) continue;
                float vx = acc[mt][nt][half * 2];
                float vy = acc[mt][nt][half * 2 + 1];
                if (MODE == 0) {
                    *(float2*)&C[(size_t)row * 128 + colg] = make_float2(vx, vy);
                } else if (MODE == 3) {
                    if (colg < 128) {
                        // u = sigmoid(z_pre + b_z), fused here
                        float2 zb = *(const float2*)&p2[colg];
                        *(float2*)&C[(size_t)row * 128 + colg] =
                            make_float2(sigmoidf_(vx + zb.x), sigmoidf_(vy + zb.y));
                    } else {
                        int cc = colg - 128;
                        float2 hv = *(const float2*)&p0[(size_t)row * 128 + cc];
                        float2 bb = *(const float2*)&p1[cc];
                        float rx = sigmoidf_(vx + bb.x) * hv.x;
                        float ry = sigmoidf_(vy + bb.y) * hv.y;
                        uint32_t lo;
                        uint32_t hi = pk2(rx, ry, lo);
                        size_t idx = ((size_t)row * 128 + cc) >> 1;
                        ((uint32_t*)sph)[idx] = hi;
                        ((uint32_t*)spl)[idx] = lo;
                    }
                } else {  // MODE 2: u precomputed in p0
                    size_t base = (size_t)row * 128 + colg;
                    float2 uu = *(const float2*)&p0[base];
                    float2 hv = *(const float2*)&p1[base];
                    float2 vbc = *(const float2*)&p3[colg];
                    float c0 = tanhf(vx + vbc.x);
                    float c1 = tanhf(vy + vbc.y);
                    *(float2*)&C[base] = make_float2((1.f - uu.x) * hv.x + uu.x * c0,
                                                     (1.f - uu.y) * hv.y + uu.y * c1);
                }
            }
        }
}

// ---------------- CSR aggregation: warp per dst node ----------------
template <int LAYER>
__global__ __launch_bounds__(256) void k_agg_csr(const float* __restrict__ b) {
    int w = blockIdx.x * 8 + (threadIdx.x >> 5);
    if (w >= NN) return;
    int lane = threadIdx.x & 31;
    const float4* xw4 = (const float4*)g_xw;

    float dd = g_deg[w];
    float4 acc = xw4[(size_t)w * 32 + lane];
    float cself = dd * dd;
    acc.x *= cself; acc.y *= cself; acc.z *= cself; acc.w *= cself;

    int start = g_rowptr[w], end = g_rowptr[w + 1];
    for (int base = start; base < end; base += 32) {
        int e = base + lane;
        int sv = 0; float dv = 0.f;
        if (e < end) { sv = g_csrsrc[e]; dv = g_deg[sv]; }
        int cnt = end - base; if (cnt > 32) cnt = 32;
        for (int j = 0; j < cnt; j++) {
            int s = __shfl_sync(0xffffffffu, sv, j);
            float c = __shfl_sync(0xffffffffu, dv, j) * dd;
            float4 v = xw4[(size_t)s * 32 + lane];
            acc.x += v.x * c; acc.y += v.y * c; acc.z += v.z * c; acc.w += v.w * c;
        }
    }

    float4 bb = *(const float4*)&b[lane * 4];
    acc.x += bb.x; acc.y += bb.y; acc.z += bb.z; acc.w += bb.w;
    if (LAYER == 1) {
        acc.x = fmaxf(acc.x, 0.f); acc.y = fmaxf(acc.y, 0.f);
        acc.z = fmaxf(acc.z, 0.f); acc.w = fmaxf(acc.w, 0.f);
    }
    uint32_t l0, l1;
    uint32_t h0 = pk2(acc.x, acc.y, l0);
    uint32_t h1 = pk2(acc.z, acc.w, l1);
    if (LAYER == 1) {
        ((uint2*)g_h1h)[(size_t)w * 32 + lane] = make_uint2(h0, h1);
        ((uint2*)g_h1l)[(size_t)w * 32 + lane] = make_uint2(l0, l1);
    } else {
        ((uint2*)g_cbh)[(size_t)w * 32 + lane] = make_uint2(h0, h1);
        ((uint2*)g_cbl)[(size_t)w * 32 + lane] = make_uint2(l0, l1);
    }
}

// ---------------- launcher ----------------
extern "C" void kernel_launch(void* const* d_in, const int* in_sizes, int n_in,
                              void* d_out, int out_size) {
    const float* x     = (const float*)d_in[0];
    const float* h     = (const float*)d_in[1];
    const int*   edge  = (const int*)d_in[2];
    const float* W_in  = (const float*)d_in[3];
    const float* b_in  = (const float*)d_in[4];
    const float* W_hid = (const float*)d_in[5];
    const float* b_hid = (const float*)d_in[6];
    const float* W_z   = (const float*)d_in[7];
    const float* b_z   = (const float*)d_in[8];
    const float* W_r   = (const float*)d_in[9];
    const float* b_r   = (const float*)d_in[10];
    const float* W_c   = (const float*)d_in[11];
    const float* b_c   = (const float*)d_in[12];
    float* out = (float*)d_out;

    const int N = in_sizes[0] / 128;
    const int E = in_sizes[2] / 2;

    float *p_xw, *p_zr;
    __nv_bfloat16 *p_bh, *p_bl, *p_xh, *p_xl, *p_hh, *p_hl, *p_h1h, *p_h1l, *p_cbh, *p_cbl;
    cudaGetSymbolAddress((void**)&p_xw,  g_xw);
    cudaGetSymbolAddress((void**)&p_zr,  g_zr);
    cudaGetSymbolAddress((void**)&p_bh,  g_bthi);
    cudaGetSymbolAddress((void**)&p_bl,  g_btlo);
    cudaGetSymbolAddress((void**)&p_xh,  g_xh);
    cudaGetSymbolAddress((void**)&p_xl,  g_xl);
    cudaGetSymbolAddress((void**)&p_hh,  g_hh);
    cudaGetSymbolAddress((void**)&p_hl,  g_hl);
    cudaGetSymbolAddress((void**)&p_h1h, g_h1h);
    cudaGetSymbolAddress((void**)&p_h1l, g_h1l);
    cudaGetSymbolAddress((void**)&p_cbh, g_cbh);
    cudaGetSymbolAddress((void**)&p_cbl, g_cbl);

    cudaFuncSetAttribute((const void*)k_gemm64<128, 0>, cudaFuncAttributeMaxDynamicSharedMemorySize, GSMEM);
    cudaFuncSetAttribute((const void*)k_gemm64<256, 3>, cudaFuncAttributeMaxDynamicSharedMemorySize, GSMEM);
    cudaFuncSetAttribute((const void*)k_gemm64<256, 2>, cudaFuncAttributeMaxDynamicSharedMemorySize, GSMEM);

    static cudaStream_t s1 = nullptr;
    static cudaEvent_t evA = nullptr, evCsr = nullptr;
    static bool tried = false;
    if (!tried) {
        tried = true;
        if (cudaStreamCreateWithFlags(&s1, cudaStreamNonBlocking) != cudaSuccess) s1 = nullptr;
        if (s1) {
            bool ok = cudaEventCreateWithFlags(&evA, cudaEventDisableTiming) == cudaSuccess &&
                      cudaEventCreateWithFlags(&evCsr, cudaEventDisableTiming) == cudaSuccess;
            if (!ok) s1 = nullptr;
        }
    }
    bool fork = (s1 != nullptr);
    cudaStream_t sSide = fork ? s1 : (cudaStream_t)0;

    const int T = 256;
    const int mt64 = (N + 63) / 64;       // 782
    dim3 g1(mt64, 1), g2(mt64, 2);
    const int aggB = (NN + 7) / 8;

    // setup (stream 0): zero cnt + weight split + x,h splits
    k_setup<<<(NN * 32 + T - 1) / T, T>>>(x, h, W_in, W_hid, W_z, W_r, W_c);

    if (fork) { cudaEventRecord(evA, 0); cudaStreamWaitEvent(sSide, evA, 0); }

    // side lane: CSR build
    k_hist<<<(E + T - 1) / T, T, 0, sSide>>>(edge + E, E);
    k_scan_block<<<NB, 256, 0, sSide>>>();
    k_scan_fin<<<NB, 256, 0, sSide>>>(E);
    k_scatter<<<(E + T - 1) / T, T, 0, sSide>>>(edge, E);
    if (fork) cudaEventRecord(evCsr, sSide);

    // main lane
    k_gemm64<128, 0><<<g1, T, GSMEM>>>(p_xh, p_xl, p_xh, p_xl, p_bh, p_bl, N,
                                       p_xw, nullptr, nullptr,
                                       nullptr, nullptr, nullptr, nullptr);
    if (fork) cudaStreamWaitEvent((cudaStream_t)0, evCsr, 0);
    k_agg_csr<1><<<aggB, T>>>(b_in);

    k_gemm64<128, 0><<<g1, T, GSMEM>>>(p_h1h, p_h1l, p_h1h, p_h1l,
                                       p_bh + 16384, p_bl + 16384, N,
                                       p_xw, nullptr, nullptr,
                                       nullptr, nullptr, nullptr, nullptr);
    k_agg_csr<2><<<aggB, T>>>(b_hid);

    // gates: [z|r] = [emb|h] @ [Wz|Wr]; y0 -> u = sigmoid(z+bz); y1 -> rh splits (reuse g_h1)
    k_gemm64<256, 3><<<g2, T, GSMEM>>>(p_cbh, p_cbl, p_hh, p_hl,
                                       p_bh + 32768, p_bl + 32768, N,
                                       p_zr, p_h1h, p_h1l,
                                       h, b_r, b_z, nullptr);

    // final: out = (1-u)*h + u*tanh([emb|rh]@Wc + b_c)
    k_gemm64<256, 2><<<g1, T, GSMEM>>>(p_cbh, p_cbl, p_h1h, p_h1l,
                                       p_bh + 98304, p_bl + 98304, N,
                                       out, nullptr, nullptr,
                                       p_zr, h, nullptr, b_c);
}

// round 17
// speedup vs baseline: 1.1759x; 1.0229x over previous
#include <cuda_runtime.h>
#include <cuda_bf16.h>
#include <cstdint>

#define NN 50000
#define NB ((NN + 255) / 256)   // 196

// ---------------- scratch ----------------
__device__ __align__(16) float g_deg[NN];
__device__ __align__(16) int   g_cnt[NN];
__device__ __align__(16) int   g_rowptr[NN + 1];
__device__ __align__(16) int   g_cursor[NN];
__device__ __align__(16) int   g_bsum[256];
__device__ __align__(16) int   g_csrsrc[600000];
__device__ __align__(16) float g_xw[(size_t)NN * 128];     // GEMM out / gather table
__device__ __align__(16) float g_zr[(size_t)NN * 128];     // u = sigmoid(z_pre + b_z)
__device__ __align__(16) __nv_bfloat16 g_xh[(size_t)NN * 128],  g_xl[(size_t)NN * 128];   // x splits
__device__ __align__(16) __nv_bfloat16 g_hh[(size_t)NN * 128],  g_hl[(size_t)NN * 128];   // h splits
__device__ __align__(16) __nv_bfloat16 g_h1h[(size_t)NN * 128], g_h1l[(size_t)NN * 128];  // h1, later rh
__device__ __align__(16) __nv_bfloat16 g_cbh[(size_t)NN * 128], g_cbl[(size_t)NN * 128];  // emb splits
__device__ __align__(16) __nv_bfloat16 g_bthi[131072], g_btlo[131072];

// HW tanh (MUFU.TANH, sm_75+). Max rel err ~2^-11; typical ~1e-5.
__device__ __forceinline__ float tanh_fast(float x) {
    float r;
    asm("tanh.approx.f32 %0, %1;" : "=f"(r) : "f"(x));
    return r;
}
// sigmoid(x) = 0.5 * tanh(x/2) + 0.5 (exact identity; approx only via tanh HW unit)
__device__ __forceinline__ float sigmoid_fast(float x) {
    return fmaf(tanh_fast(x * 0.5f), 0.5f, 0.5f);
}

__device__ __forceinline__ uint32_t smem_u32(const void* p) {
    uint32_t a;
    asm("{ .reg .u64 t; cvta.to.shared.u64 t, %1; cvt.u32.u64 %0, t; }" : "=r"(a) : "l"(p));
    return a;
}
__device__ __forceinline__ void ldsm4(uint32_t& r0, uint32_t& r1, uint32_t& r2, uint32_t& r3,
                                      uint32_t addr) {
    asm volatile("ldmatrix.sync.aligned.m8n8.x4.shared.b16 {%0,%1,%2,%3}, [%4];"
                 : "=r"(r0), "=r"(r1), "=r"(r2), "=r"(r3) : "r"(addr));
}
__device__ __forceinline__ void mma16816(float* d, const uint32_t* a, uint32_t b0, uint32_t b1) {
    asm volatile(
        "mma.sync.aligned.m16n8k16.row.col.f32.bf16.bf16.f32 "
        "{%0,%1,%2,%3}, {%4,%5,%6,%7}, {%8,%9}, {%0,%1,%2,%3};"
        : "+f"(d[0]), "+f"(d[1]), "+f"(d[2]), "+f"(d[3])
        : "r"(a[0]), "r"(a[1]), "r"(a[2]), "r"(a[3]), "r"(b0), "r"(b1));
}
__device__ __forceinline__ uint32_t pk2(float x, float y, uint32_t& lo2) {
    __nv_bfloat16 hx = __float2bfloat16(x), hy = __float2bfloat16(y);
    __nv_bfloat16 lx = __float2bfloat16(x - __bfloat162float(hx));
    __nv_bfloat16 ly = __float2bfloat16(y - __bfloat162float(hy));
    lo2 = ((uint32_t)__bfloat16_as_ushort(ly) << 16) | __bfloat16_as_ushort(lx);
    return ((uint32_t)__bfloat16_as_ushort(hy) << 16) | __bfloat16_as_ushort(hx);
}

// ---------------- fused setup: zero cnt + weight split + x,h splits ----------------
// weight layout (bf16 elems):
//   0:      Win^T   128 rows, ldk 128
//   16384:  Whid^T  128 rows, ldk 128
//   32768:  [Wz|Wr]^T 256 rows, ldk 256
//   98304:  Wc^T    128 rows, ldk 256
__global__ void k_setup(const float* __restrict__ x, const float* __restrict__ h,
                        const float* __restrict__ Win, const float* __restrict__ Whid,
                        const float* __restrict__ Wz, const float* __restrict__ Wr,
                        const float* __restrict__ Wc) {
    int idx = blockIdx.x * blockDim.x + threadIdx.x;
    if (idx < NN) g_cnt[idx] = 0;
    if (idx < 131072) {
        float v; int dst;
        if (idx < 16384) {
            int k = idx >> 7, n = idx & 127;
            v = Win[idx]; dst = n * 128 + k;
        } else if (idx < 32768) {
            int i2 = idx - 16384; int k = i2 >> 7, n = i2 & 127;
            v = Whid[i2]; dst = 16384 + n * 128 + k;
        } else if (idx < 65536) {
            int i2 = idx - 32768; int k = i2 >> 7, n = i2 & 127;
            v = Wz[i2]; dst = 32768 + n * 256 + k;
        } else if (idx < 98304) {
            int i2 = idx - 65536; int k = i2 >> 7, n = i2 & 127;
            v = Wr[i2]; dst = 32768 + (128 + n) * 256 + k;
        } else {
            int i2 = idx - 98304; int k = i2 >> 7, n = i2 & 127;
            v = Wc[i2]; dst = 98304 + n * 256 + k;
        }
        __nv_bfloat16 hi = __float2bfloat16(v);
        __nv_bfloat16 lo = __float2bfloat16(v - __bfloat162float(hi));
        g_bthi[dst] = hi;
        g_btlo[dst] = lo;
    }
    if (idx < NN * 32) {
        float4 v = ((const float4*)x)[idx];
        uint32_t l0, l1;
        uint32_t h0 = pk2(v.x, v.y, l0);
        uint32_t h1 = pk2(v.z, v.w, l1);
        ((uint2*)g_xh)[idx] = make_uint2(h0, h1);
        ((uint2*)g_xl)[idx] = make_uint2(l0, l1);
        float4 w = ((const float4*)h)[idx];
        uint32_t m0, m1;
        uint32_t g0 = pk2(w.x, w.y, m0);
        uint32_t g1 = pk2(w.z, w.w, m1);
        ((uint2*)g_hh)[idx] = make_uint2(g0, g1);
        ((uint2*)g_hl)[idx] = make_uint2(m0, m1);
    }
}

// ---------------- CSR build ----------------
__global__ void k_hist(const int* __restrict__ dst, int E) {
    int i = blockIdx.x * blockDim.x + threadIdx.x;
    if (i < E) atomicAdd(&g_cnt[dst[i]], 1);
}
__global__ void k_scan_block() {
    __shared__ int sh[256];
    int tid = threadIdx.x;
    int i = blockIdx.x * 256 + tid;
    int v = (i < NN) ? g_cnt[i] : 0;
    sh[tid] = v;
    __syncthreads();
#pragma unroll
    for (int off = 1; off < 256; off <<= 1) {
        int t = (tid >= off) ? sh[tid - off] : 0;
        __syncthreads();
        sh[tid] += t;
        __syncthreads();
    }
    if (i < NN) g_rowptr[i] = sh[tid] - v;
    if (tid == 255) g_bsum[blockIdx.x] = sh[255];
}
__global__ void k_scan_fin(int E) {
    __shared__ int sh[256];
    int tid = threadIdx.x;
    int v = (tid < NB) ? g_bsum[tid] : 0;
    sh[tid] = v;
    __syncthreads();
#pragma unroll
    for (int off = 1; off < 256; off <<= 1) {
        int t = (tid >= off) ? sh[tid - off] : 0;
        __syncthreads();
        sh[tid] += t;
        __syncthreads();
    }
    __shared__ int s_off;
    if (tid == 0) s_off = sh[blockIdx.x] - g_bsum[blockIdx.x];
    __syncthreads();
    int i = blockIdx.x * 256 + tid;
    if (i >= NN) return;
    int r = g_rowptr[i] + s_off;
    g_rowptr[i] = r;
    g_cursor[i] = r;
    g_deg[i] = rsqrtf((float)(g_cnt[i] + 1));
    if (i == NN - 1) g_rowptr[NN] = E;
}
__global__ void k_scatter(const int* __restrict__ edge, int E) {
    int i = blockIdx.x * blockDim.x + threadIdx.x;
    if (i >= E) return;
    int d = edge[E + i];
    int pos = atomicAdd(&g_cursor[d], 1);
    g_csrsrc[pos] = edge[i];
}

// ---------------- HMMA GEMM: 64x128 tile, chunk-indexed A plane pairs ----------------
#define PLA 5120
#define PLB 10240
#define BUFS (2 * PLA + 2 * PLB)
#define GSMEM (2 * BUFS)
#define AHI_O 0
#define ALO_O PLA
#define BHI_O (2 * PLA)
#define BLO_O (2 * PLA + PLB)

// A given as two [M,128] plane pairs; chunks 0-3 read pair0, chunks 4-7 pair1 (KT=256).
// MODE 0: C = acc.
// MODE 3: y0 -> u = sigmoid(acc + bz); y1 -> rh = sigmoid(acc + br)*h -> splits.
// MODE 2: out = (1-u)*h + u*tanh(acc + bc)   (u precomputed in zr)
template <int KT, int MODE>
__global__ __launch_bounds__(256, 3) void k_gemm64(
    const __nv_bfloat16* __restrict__ Ah0, const __nv_bfloat16* __restrict__ Al0,
    const __nv_bfloat16* __restrict__ Ah1, const __nv_bfloat16* __restrict__ Al1,
    const __nv_bfloat16* __restrict__ Bh, const __nv_bfloat16* __restrict__ Bl,
    int M, float* __restrict__ C,
    __nv_bfloat16* __restrict__ sph, __nv_bfloat16* __restrict__ spl,
    const float* __restrict__ p0, const float* __restrict__ p1,
    const float* __restrict__ p2, const float* __restrict__ p3)
{
    extern __shared__ char smem[];
    uint32_t sb = smem_u32(smem);
    int tid = threadIdx.x, lane = tid & 31, wid = tid >> 5;
    int wm = (wid >> 2) * 32, wn = (wid & 3) * 32;
    int bm = blockIdx.x * 64, bn = blockIdx.y * 128;

    float acc[2][4][4];
#pragma unroll
    for (int i = 0; i < 2; i++)
#pragma unroll
        for (int j = 0; j < 4; j++)
#pragma unroll
            for (int t = 0; t < 4; t++) acc[i][j][t] = 0.f;

    uint32_t aRow = lane & 15;
    uint32_t aK   = (lane >> 1) & 8;
    uint32_t bRow = (lane & 7) + ((lane >> 4) & 1) * 8;
    uint32_t bK   = ((lane >> 3) & 1) * 8;

    int arow = tid >> 2, aseg = tid & 3;

    auto load_chunk = [&](int buf, int c) {
        uint32_t bufb = sb + buf * BUFS;
        const __nv_bfloat16* ah = (KT > 128 && c >= 4) ? Ah1 : Ah0;
        const __nv_bfloat16* al = (KT > 128 && c >= 4) ? Al1 : Al0;
        int ka = (c & 3) << 5;
        int gra = min(bm + arow, M - 1);
        {
            const __nv_bfloat16* src = ah + (size_t)gra * 128 + ka + aseg * 8;
            uint32_t dst = bufb + AHI_O + arow * 80 + aseg * 16;
            asm volatile("cp.async.cg.shared.global [%0], [%1], 16;" :: "r"(dst), "l"(src));
        }
        {
            const __nv_bfloat16* src = al + (size_t)gra * 128 + ka + aseg * 8;
            uint32_t dst = bufb + ALO_O + arow * 80 + aseg * 16;
            asm volatile("cp.async.cg.shared.global [%0], [%1], 16;" :: "r"(dst), "l"(src));
        }
        int kb = c << 5;
#pragma unroll
        for (int it = 0; it < 2; it++) {
            int i = tid + it * 256;
            int row = i >> 2, seg = i & 3;
            const __nv_bfloat16* srch = Bh + (size_t)(bn + row) * KT + kb + seg * 8;
            const __nv_bfloat16* srcl = Bl + (size_t)(bn + row) * KT + kb + seg * 8;
            uint32_t dsth = bufb + BHI_O + row * 80 + seg * 16;
            uint32_t dstl = bufb + BLO_O + row * 80 + seg * 16;
            asm volatile("cp.async.cg.shared.global [%0], [%1], 16;" :: "r"(dsth), "l"(srch));
            asm volatile("cp.async.cg.shared.global [%0], [%1], 16;" :: "r"(dstl), "l"(srcl));
        }
        asm volatile("cp.async.commit_group;" ::: "memory");
    };

    auto compute_chunk = [&](int buf) {
        uint32_t base = sb + buf * BUFS;
#pragma unroll
        for (int ks = 0; ks < 2; ks++) {
            uint32_t ah[2][4], al[2][4];
#pragma unroll
            for (int mt = 0; mt < 2; mt++) {
                uint32_t ao = base + AHI_O + (wm + mt * 16 + aRow) * 80 + (ks * 16 + aK) * 2;
                ldsm4(ah[mt][0], ah[mt][1], ah[mt][2], ah[mt][3], ao);
                ldsm4(al[mt][0], al[mt][1], al[mt][2], al[mt][3], ao + (ALO_O - AHI_O));
            }
#pragma unroll
            for (int np = 0; np < 2; np++) {
                uint32_t bo = base + BHI_O + (wn + np * 16 + bRow) * 80 + (ks * 16 + bK) * 2;
                uint32_t bh[4], bl[4];
                ldsm4(bh[0], bh[1], bh[2], bh[3], bo);
                ldsm4(bl[0], bl[1], bl[2], bl[3], bo + (BLO_O - BHI_O));
#pragma unroll
                for (int mt = 0; mt < 2; mt++) {
                    mma16816(acc[mt][np * 2],     ah[mt], bh[0], bh[1]);
                    mma16816(acc[mt][np * 2],     ah[mt], bl[0], bl[1]);
                    mma16816(acc[mt][np * 2],     al[mt], bh[0], bh[1]);
                    mma16816(acc[mt][np * 2 + 1], ah[mt], bh[2], bh[3]);
                    mma16816(acc[mt][np * 2 + 1], ah[mt], bl[2], bl[3]);
                    mma16816(acc[mt][np * 2 + 1], al[mt], bh[2], bh[3]);
                }
            }
        }
    };

    const int nc = KT >> 5;
    load_chunk(0, 0);
#pragma unroll
    for (int c = 0; c < nc; c++) {
        if (c + 1 < nc) {
            load_chunk((c + 1) & 1, c + 1);
            asm volatile("cp.async.wait_group 1;" ::: "memory");
        } else {
            asm volatile("cp.async.wait_group 0;" ::: "memory");
        }
        __syncthreads();
        compute_chunk(c & 1);
        __syncthreads();
    }

    // ---------------- epilogue ----------------
#pragma unroll
    for (int mt = 0; mt < 2; mt++)
#pragma unroll
        for (int nt = 0; nt < 4; nt++) {
            int colg = bn + wn + nt * 8 + ((lane & 3) << 1);
            int rbase = bm + wm + mt * 16 + (lane >> 2);
#pragma unroll
            for (int half = 0; half < 2; half++) {
                int row = rbase + half * 8;
                if (row >= M) continue;
                float vx = acc[mt][nt][half * 2];
                float vy = acc[mt][nt][half * 2 + 1];
                if (MODE == 0) {
                    *(float2*)&C[(size_t)row * 128 + colg] = make_float2(vx, vy);
                } else if (MODE == 3) {
                    if (colg < 128) {
                        float2 zb = *(const float2*)&p2[colg];
                        *(float2*)&C[(size_t)row * 128 + colg] =
                            make_float2(sigmoid_fast(vx + zb.x), sigmoid_fast(vy + zb.y));
                    } else {
                        int cc = colg - 128;
                        float2 hv = *(const float2*)&p0[(size_t)row * 128 + cc];
                        float2 bb = *(const float2*)&p1[cc];
                        float rx = sigmoid_fast(vx + bb.x) * hv.x;
                        float ry = sigmoid_fast(vy + bb.y) * hv.y;
                        uint32_t lo;
                        uint32_t hi = pk2(rx, ry, lo);
                        size_t idx = ((size_t)row * 128 + cc) >> 1;
                        ((uint32_t*)sph)[idx] = hi;
                        ((uint32_t*)spl)[idx] = lo;
                    }
                } else {  // MODE 2: u precomputed in p0
                    size_t base = (size_t)row * 128 + colg;
                    float2 uu = *(const float2*)&p0[base];
                    float2 hv = *(const float2*)&p1[base];
                    float2 vbc = *(const float2*)&p3[colg];
                    float c0 = tanh_fast(vx + vbc.x);
                    float c1 = tanh_fast(vy + vbc.y);
                    *(float2*)&C[base] = make_float2((1.f - uu.x) * hv.x + uu.x * c0,
                                                     (1.f - uu.y) * hv.y + uu.y * c1);
                }
            }
        }
}

// ---------------- CSR aggregation: warp per dst node ----------------
template <int LAYER>
__global__ __launch_bounds__(256) void k_agg_csr(const float* __restrict__ b) {
    int w = blockIdx.x * 8 + (threadIdx.x >> 5);
    if (w >= NN) return;
    int lane = threadIdx.x & 31;
    const float4* xw4 = (const float4*)g_xw;

    float dd = g_deg[w];
    float4 acc = xw4[(size_t)w * 32 + lane];
    float cself = dd * dd;
    acc.x *= cself; acc.y *= cself; acc.z *= cself; acc.w *= cself;

    int start = g_rowptr[w], end = g_rowptr[w + 1];
    for (int base = start; base < end; base += 32) {
        int e = base + lane;
        int sv = 0; float dv = 0.f;
        if (e < end) { sv = g_csrsrc[e]; dv = g_deg[sv]; }
        int cnt = end - base; if (cnt > 32) cnt = 32;
        for (int j = 0; j < cnt; j++) {
            int s = __shfl_sync(0xffffffffu, sv, j);
            float c = __shfl_sync(0xffffffffu, dv, j) * dd;
            float4 v = xw4[(size_t)s * 32 + lane];
            acc.x += v.x * c; acc.y += v.y * c; acc.z += v.z * c; acc.w += v.w * c;
        }
    }

    float4 bb = *(const float4*)&b[lane * 4];
    acc.x += bb.x; acc.y += bb.y; acc.z += bb.z; acc.w += bb.w;
    if (LAYER == 1) {
        acc.x = fmaxf(acc.x, 0.f); acc.y = fmaxf(acc.y, 0.f);
        acc.z = fmaxf(acc.z, 0.f); acc.w = fmaxf(acc.w, 0.f);
    }
    uint32_t l0, l1;
    uint32_t h0 = pk2(acc.x, acc.y, l0);
    uint32_t h1 = pk2(acc.z, acc.w, l1);
    if (LAYER == 1) {
        ((uint2*)g_h1h)[(size_t)w * 32 + lane] = make_uint2(h0, h1);
        ((uint2*)g_h1l)[(size_t)w * 32 + lane] = make_uint2(l0, l1);
    } else {
        ((uint2*)g_cbh)[(size_t)w * 32 + lane] = make_uint2(h0, h1);
        ((uint2*)g_cbl)[(size_t)w * 32 + lane] = make_uint2(l0, l1);
    }
}

// ---------------- launcher ----------------
extern "C" void kernel_launch(void* const* d_in, const int* in_sizes, int n_in,
                              void* d_out, int out_size) {
    const float* x     = (const float*)d_in[0];
    const float* h     = (const float*)d_in[1];
    const int*   edge  = (const int*)d_in[2];
    const float* W_in  = (const float*)d_in[3];
    const float* b_in  = (const float*)d_in[4];
    const float* W_hid = (const float*)d_in[5];
    const float* b_hid = (const float*)d_in[6];
    const float* W_z   = (const float*)d_in[7];
    const float* b_z   = (const float*)d_in[8];
    const float* W_r   = (const float*)d_in[9];
    const float* b_r   = (const float*)d_in[10];
    const float* W_c   = (const float*)d_in[11];
    const float* b_c   = (const float*)d_in[12];
    float* out = (float*)d_out;

    const int N = in_sizes[0] / 128;
    const int E = in_sizes[2] / 2;

    float *p_xw, *p_zr;
    __nv_bfloat16 *p_bh, *p_bl, *p_xh, *p_xl, *p_hh, *p_hl, *p_h1h, *p_h1l, *p_cbh, *p_cbl;
    cudaGetSymbolAddress((void**)&p_xw,  g_xw);
    cudaGetSymbolAddress((void**)&p_zr,  g_zr);
    cudaGetSymbolAddress((void**)&p_bh,  g_bthi);
    cudaGetSymbolAddress((void**)&p_bl,  g_btlo);
    cudaGetSymbolAddress((void**)&p_xh,  g_xh);
    cudaGetSymbolAddress((void**)&p_xl,  g_xl);
    cudaGetSymbolAddress((void**)&p_hh,  g_hh);
    cudaGetSymbolAddress((void**)&p_hl,  g_hl);
    cudaGetSymbolAddress((void**)&p_h1h, g_h1h);
    cudaGetSymbolAddress((void**)&p_h1l, g_h1l);
    cudaGetSymbolAddress((void**)&p_cbh, g_cbh);
    cudaGetSymbolAddress((void**)&p_cbl, g_cbl);

    cudaFuncSetAttribute((const void*)k_gemm64<128, 0>, cudaFuncAttributeMaxDynamicSharedMemorySize, GSMEM);
    cudaFuncSetAttribute((const void*)k_gemm64<256, 3>, cudaFuncAttributeMaxDynamicSharedMemorySize, GSMEM);
    cudaFuncSetAttribute((const void*)k_gemm64<256, 2>, cudaFuncAttributeMaxDynamicSharedMemorySize, GSMEM);

    static cudaStream_t s1 = nullptr;
    static cudaEvent_t evA = nullptr, evCsr = nullptr;
    static bool tried = false;
    if (!tried) {
        tried = true;
        if (cudaStreamCreateWithFlags(&s1, cudaStreamNonBlocking) != cudaSuccess) s1 = nullptr;
        if (s1) {
            bool ok = cudaEventCreateWithFlags(&evA, cudaEventDisableTiming) == cudaSuccess &&
                      cudaEventCreateWithFlags(&evCsr, cudaEventDisableTiming) == cudaSuccess;
            if (!ok) s1 = nullptr;
        }
    }
    bool fork = (s1 != nullptr);
    cudaStream_t sSide = fork ? s1 : (cudaStream_t)0;

    const int T = 256;
    const int mt64 = (N + 63) / 64;       // 782
    dim3 g1(mt64, 1), g2(mt64, 2);
    const int aggB = (NN + 7) / 8;

    // setup (stream 0): zero cnt + weight split + x,h splits
    k_setup<<<(NN * 32 + T - 1) / T, T>>>(x, h, W_in, W_hid, W_z, W_r, W_c);

    if (fork) { cudaEventRecord(evA, 0); cudaStreamWaitEvent(sSide, evA, 0); }

    // side lane: CSR build
    k_hist<<<(E + T - 1) / T, T, 0, sSide>>>(edge + E, E);
    k_scan_block<<<NB, 256, 0, sSide>>>();
    k_scan_fin<<<NB, 256, 0, sSide>>>(E);
    k_scatter<<<(E + T - 1) / T, T, 0, sSide>>>(edge, E);
    if (fork) cudaEventRecord(evCsr, sSide);

    // main lane
    k_gemm64<128, 0><<<g1, T, GSMEM>>>(p_xh, p_xl, p_xh, p_xl, p_bh, p_bl, N,
                                       p_xw, nullptr, nullptr,
                                       nullptr, nullptr, nullptr, nullptr);
    if (fork) cudaStreamWaitEvent((cudaStream_t)0, evCsr, 0);
    k_agg_csr<1><<<aggB, T>>>(b_in);

    k_gemm64<128, 0><<<g1, T, GSMEM>>>(p_h1h, p_h1l, p_h1h, p_h1l,
                                       p_bh + 16384, p_bl + 16384, N,
                                       p_xw, nullptr, nullptr,
                                       nullptr, nullptr, nullptr, nullptr);
    k_agg_csr<2><<<aggB, T>>>(b_hid);

    // gates: [z|r] = [emb|h] @ [Wz|Wr]; y0 -> u = sigmoid(z+bz); y1 -> rh splits (reuse g_h1)
    k_gemm64<256, 3><<<g2, T, GSMEM>>>(p_cbh, p_cbl, p_hh, p_hl,
                                       p_bh + 32768, p_bl + 32768, N,
                                       p_zr, p_h1h, p_h1l,
                                       h, b_r, b_z, nullptr);

    // final: out = (1-u)*h + u*tanh([emb|rh]@Wc + b_c)
    k_gemm64<256, 2><<<g1, T, GSMEM>>>(p_cbh, p_cbl, p_h1h, p_h1l,
                                       p_bh + 98304, p_bl + 98304, N,
                                       out, nullptr, nullptr,
                                       p_zr, h, nullptr, b_c);
}